// round 6
// baseline (speedup 1.0000x reference)
#include <cuda_runtime.h>
#include <math.h>

#define BB    64
#define TT    400
#define NN    1024
#define NINC  128
#define NOUTC 32
#define BN    (BB * NN)

// ---------------- device scratch (static: no runtime allocation) ----------------
__device__ __align__(128) float g_W[3 * NN * NN];   // 12 MB   dmap * sign * |w|
__device__ __align__(128) float g_inp[TT * BN];     // 105 MB  inputs @ w_in, [t][b][n]
__device__ __align__(128) float g_mem[BN];
__device__ __align__(128) float g_wp[BN];
__device__ __align__(128) float g_act[5 * BN];      // ring: out*(1+wp), slot t%5
__device__ __align__(128) float g_out[BN];          // spikes of most recent step
__device__ __align__(128) float g_part[8 * BN];     // split-K partial sums
__device__ __align__(128) float g_r[BB * NOUTC];    // readout leaky state

// ---------------- zero state (runs at the start of every replay) ----------------
__global__ void k_init() {
    int i = blockIdx.x * 256 + threadIdx.x;
    const int st = 64 * 256;
    for (int j = i; j < BN; j += st) { g_mem[j] = 0.f; g_wp[j] = 0.f; g_out[j] = 0.f; }
    for (int j = i; j < 5 * BN; j += st) g_act[j] = 0.f;
    for (int j = i; j < BB * NOUTC; j += st) g_r[j] = 0.f;
}

// ---------------- W[d][e][o] = dmap * (sign[e] * |w[e][o]|) ---------------------
__global__ void k_prep(const float* __restrict__ w, const float* __restrict__ ws,
                       const float* __restrict__ dmap) {
    int i = blockIdx.x * 256 + threadIdx.x;          // 3*1024*1024 threads total
    int eo = i & (NN * NN - 1);
    g_W[i] = dmap[i] * (ws[eo >> 10] * fabsf(w[eo]));
}

// ------------- input projection: g_inp[t][b][n] = inputs[b][t][:] @ w_in --------
__global__ __launch_bounds__(256) void k_inp(const float* __restrict__ inputs,
                                             const float* __restrict__ w_in) {
    __shared__ float A_sm[64 * 33];
    __shared__ float W_sm[32 * 64];
    const int bx = blockIdx.x;
    const int mt = bx >> 4;                          // t
    const int nt = bx & 15;                          // 64-wide o tile
    const int tid = threadIdx.x;
    const int mq = tid >> 4, nq = tid & 15;
    float acc[16];
#pragma unroll
    for (int i = 0; i < 16; i++) acc[i] = 0.f;

    for (int c0 = 0; c0 < NINC; c0 += 32) {
        int kk = tid & 31, rb = tid >> 5;
#pragma unroll
        for (int j = 0; j < 8; j++) {
            int row = rb + 8 * j;
            A_sm[row * 33 + kk] = inputs[row * (TT * NINC) + mt * NINC + c0 + kk];
        }
        int ol = tid & 63, kl = tid >> 6;
#pragma unroll
        for (int j = 0; j < 8; j++) {
            int k2 = kl + 4 * j;
            W_sm[k2 * 64 + ol] = w_in[(c0 + k2) * NN + nt * 64 + ol];
        }
        __syncthreads();
#pragma unroll
        for (int k2 = 0; k2 < 32; k2++) {
            float4 wv = *(const float4*)&W_sm[k2 * 64 + nq * 4];
            float a0 = A_sm[(mq * 4 + 0) * 33 + k2];
            float a1 = A_sm[(mq * 4 + 1) * 33 + k2];
            float a2 = A_sm[(mq * 4 + 2) * 33 + k2];
            float a3 = A_sm[(mq * 4 + 3) * 33 + k2];
            acc[0]  += a0 * wv.x; acc[1]  += a0 * wv.y; acc[2]  += a0 * wv.z; acc[3]  += a0 * wv.w;
            acc[4]  += a1 * wv.x; acc[5]  += a1 * wv.y; acc[6]  += a1 * wv.z; acc[7]  += a1 * wv.w;
            acc[8]  += a2 * wv.x; acc[9]  += a2 * wv.y; acc[10] += a2 * wv.z; acc[11] += a2 * wv.w;
            acc[12] += a3 * wv.x; acc[13] += a3 * wv.y; acc[14] += a3 * wv.z; acc[15] += a3 * wv.w;
        }
        __syncthreads();
    }
#pragma unroll
    for (int i = 0; i < 4; i++) {
        float4 v = make_float4(acc[i * 4], acc[i * 4 + 1], acc[i * 4 + 2], acc[i * 4 + 3]);
        *(float4*)&g_inp[mt * BN + (mq * 4 + i) * NN + nt * 64 + nq * 4] = v;
    }
}

// ---- per-step: blocks 0..63 = readout of step t-1; blocks 64..191 = split-K GEMM
// GEMM(t) reads ring slots written at steps t-1 / t-2 / t-4 (delays 1,2,4; L=5),
// which are zero-initialized for t < delay — matches the reference ring buffer.
__global__ __launch_bounds__(256) void k_step(int t, const float* __restrict__ w_out,
                                              float* __restrict__ out) {
    __shared__ float A_sm[64 * 33];
    __shared__ float W_sm[32 * 64];
    __shared__ float red[256];
    const int tid = threadIdx.x;

    if (blockIdx.x < 64) {
        // ---------- readout of step t-1 (out(t-1) already in g_out) ----------
        if (t == 0) return;
        int b = blockIdx.x;
        int o = tid & 31, ch = tid >> 5;
        const float* ob = &g_out[b * NN];
        const float* wc = w_out + o;
        float s = 0.f;
        int e0 = ch * 128;
#pragma unroll 4
        for (int e = e0; e < e0 + 128; e++) s += ob[e] * wc[e * NOUTC];
        red[tid] = s;
        __syncthreads();
        if (tid < 32) {
            float h = 0.f;
#pragma unroll
            for (int c = 0; c < 8; c++) h += red[c * 32 + tid];
            float r = 0.95f * g_r[b * NOUTC + tid] + h;
            g_r[b * NOUTC + tid] = r;
            out[b * (TT * NOUTC) + (t - 1) * NOUTC + tid] = r;
        }
        return;
    }
    if (t >= TT) return;

    // ---------- split-K GEMM: syn partials. tile = 64 rows(b) x 64 cols(o) ------
    const int bq = blockIdx.x - 64;
    const int ot = bq >> 3, kb = bq & 7;             // 16 col tiles x 8 K splits
    const int obase = ot * 64;
    const int mq = tid >> 4, nq = tid & 15;
    const int kkA = tid & 31, rbA = tid >> 5;
    const int olW = tid & 63, klW = tid >> 6;
    const int s1 = (t + 4) % 5;                      // delay 1
    const int s2 = (t + 3) % 5;                      // delay 2
    const int s4 = (t + 1) % 5;                      // delay 4

    float acc[16];
#pragma unroll
    for (int i = 0; i < 16; i++) acc[i] = 0.f;

    float rA[8], rW[8];
    {
        int k0 = kb * 384;
        int d = k0 >> 10, e0 = k0 & (NN - 1);
        int sl = (d == 0) ? s1 : ((d == 1) ? s2 : s4);
        const float* Ab = &g_act[sl * BN + e0 + kkA];
#pragma unroll
        for (int j = 0; j < 8; j++) rA[j] = Ab[(rbA + 8 * j) * NN];
        const float* Wb = &g_W[d * (NN * NN) + (e0 + klW) * NN + obase + olW];
#pragma unroll
        for (int j = 0; j < 8; j++) rW[j] = Wb[4 * j * NN];
    }

    for (int c = 0; c < 12; c++) {                   // 12 chunks of K=32 (32 | 1024)
#pragma unroll
        for (int j = 0; j < 8; j++) A_sm[(rbA + 8 * j) * 33 + kkA] = rA[j];
#pragma unroll
        for (int j = 0; j < 8; j++) W_sm[(klW + 4 * j) * 64 + olW] = rW[j];
        __syncthreads();
        if (c < 11) {                                // prefetch next chunk to regs
            int k0 = kb * 384 + (c + 1) * 32;
            int d = k0 >> 10, e0 = k0 & (NN - 1);
            int sl = (d == 0) ? s1 : ((d == 1) ? s2 : s4);
            const float* Ab = &g_act[sl * BN + e0 + kkA];
#pragma unroll
            for (int j = 0; j < 8; j++) rA[j] = Ab[(rbA + 8 * j) * NN];
            const float* Wb = &g_W[d * (NN * NN) + (e0 + klW) * NN + obase + olW];
#pragma unroll
            for (int j = 0; j < 8; j++) rW[j] = Wb[4 * j * NN];
        }
#pragma unroll
        for (int k2 = 0; k2 < 32; k2++) {
            float4 wv = *(const float4*)&W_sm[k2 * 64 + nq * 4];
            float a0 = A_sm[(mq * 4 + 0) * 33 + k2];
            float a1 = A_sm[(mq * 4 + 1) * 33 + k2];
            float a2 = A_sm[(mq * 4 + 2) * 33 + k2];
            float a3 = A_sm[(mq * 4 + 3) * 33 + k2];
            acc[0]  += a0 * wv.x; acc[1]  += a0 * wv.y; acc[2]  += a0 * wv.z; acc[3]  += a0 * wv.w;
            acc[4]  += a1 * wv.x; acc[5]  += a1 * wv.y; acc[6]  += a1 * wv.z; acc[7]  += a1 * wv.w;
            acc[8]  += a2 * wv.x; acc[9]  += a2 * wv.y; acc[10] += a2 * wv.z; acc[11] += a2 * wv.w;
            acc[12] += a3 * wv.x; acc[13] += a3 * wv.y; acc[14] += a3 * wv.z; acc[15] += a3 * wv.w;
        }
        __syncthreads();
    }
#pragma unroll
    for (int i = 0; i < 4; i++) {
        float4 v = make_float4(acc[i * 4], acc[i * 4 + 1], acc[i * 4 + 2], acc[i * 4 + 3]);
        *(float4*)&g_part[kb * BN + (mq * 4 + i) * NN + obase + nq * 4] = v;
    }
}

// ---------- state update: spike, ring write, wp/mem update (fixed-order reduce) ---
__global__ __launch_bounds__(256) void k_update(int t, const float* __restrict__ p) {
    int idx = blockIdx.x * 256 + threadIdx.x;        // 16384 float4 groups
    int i4 = idx * 4;
    float4 mem  = *(float4*)&g_mem[i4];
    float4 wp   = *(float4*)&g_wp[i4];
    float4 pv   = *(const float4*)&p[i4 & (NN - 1)];
    float4 inpv = *(float4*)&g_inp[t * BN + i4];
    float4 syn  = make_float4(0.f, 0.f, 0.f, 0.f);
#pragma unroll
    for (int k = 0; k < 8; k++) {                    // deterministic split-K reduce
        float4 v = *(float4*)&g_part[k * BN + i4];
        syn.x += v.x; syn.y += v.y; syn.z += v.z; syn.w += v.w;
    }
    float o0 = mem.x > 1.f ? 1.f : 0.f;
    float o1 = mem.y > 1.f ? 1.f : 0.f;
    float o2 = mem.z > 1.f ? 1.f : 0.f;
    float o3 = mem.w > 1.f ? 1.f : 0.f;

    float4 act = make_float4(o0 * (1.f + wp.x), o1 * (1.f + wp.y),
                             o2 * (1.f + wp.z), o3 * (1.f + wp.w));
    *(float4*)&g_act[(t % 5) * BN + i4] = act;
    *(float4*)&g_out[i4] = make_float4(o0, o1, o2, o3);

    wp.x = 0.99f * wp.x + o0 * pv.x * (1.f + (pv.x < 0.f ? wp.x : 0.f));
    wp.y = 0.99f * wp.y + o1 * pv.y * (1.f + (pv.y < 0.f ? wp.y : 0.f));
    wp.z = 0.99f * wp.z + o2 * pv.z * (1.f + (pv.z < 0.f ? wp.z : 0.f));
    wp.w = 0.99f * wp.w + o3 * pv.w * (1.f + (pv.w < 0.f ? wp.w : 0.f));

    mem.x = 0.95f * mem.x + inpv.x + syn.x - o0;
    mem.y = 0.95f * mem.y + inpv.y + syn.y - o1;
    mem.z = 0.95f * mem.z + inpv.z + syn.z - o2;
    mem.w = 0.95f * mem.w + inpv.w + syn.w - o3;

    *(float4*)&g_wp[i4]  = wp;
    *(float4*)&g_mem[i4] = mem;
}

extern "C" void kernel_launch(void* const* d_in, const int* in_sizes, int n_in,
                              void* d_out, int out_size) {
    const float* inputs = (const float*)d_in[0];   // (B,T,NIN)
    const float* w      = (const float*)d_in[1];   // (N,N)
    const float* w_in   = (const float*)d_in[2];   // (NIN,N)
    const float* w_out  = (const float*)d_in[3];   // (N,NOUT)
    const float* ws     = (const float*)d_in[4];   // (N,)
    const float* dmap   = (const float*)d_in[5];   // (D,N,N)
    const float* p      = (const float*)d_in[6];   // (N,)
    // d_in[7] = delays [1,2,4] (fixed by the problem; baked into slot math)
    float* out = (float*)d_out;                    // (B,T,NOUT) float32

    k_init<<<64, 256>>>();
    k_prep<<<(3 * NN * NN) / 256, 256>>>(w, ws, dmap);
    k_inp<<<TT * 16, 256>>>(inputs, w_in);

    for (int t = 0; t <= TT; ++t) {
        k_step<<<192, 256>>>(t, w_out, out);       // readout(t-1) + GEMM(t)
        if (t < TT) k_update<<<64, 256>>>(t, p);   // spike/state update for step t
    }
}

// round 7
// speedup vs baseline: 1.2358x; 1.2358x over previous
#include <cuda_runtime.h>
#include <math.h>

#define BB    64
#define TT    400
#define NN    1024
#define NINC  128
#define NOUTC 32
#define BN    (BB * NN)
#define SPLITK 32
#define NCHUNK 6          // 96 K per CTA = 6 chunks of 16

// ---------------- device scratch (static: no runtime allocation) ----------------
__device__ __align__(128) float g_W[3 * NN * NN];     // 12 MB   dmap * sign * |w|
__device__ __align__(128) float g_inp[TT * BN];       // 105 MB  inputs @ w_in, [t][b][n]
__device__ __align__(128) float g_mem[BN];
__device__ __align__(128) float g_wp[BN];
__device__ __align__(128) float g_act[5 * BN];        // ring: out*(1+wp), slot t%5
__device__ __align__(128) float g_outd[2 * BN];       // spikes, double-buffered by t&1
__device__ __align__(128) float g_part[SPLITK * BN];  // split-K partial sums (8 MB)
__device__ __align__(128) float g_r[BB * NOUTC];      // readout leaky state

// ---------------- zero state (runs at the start of every replay) ----------------
__global__ void k_init() {
    int i = blockIdx.x * 256 + threadIdx.x;
    const int st = 64 * 256;
    for (int j = i; j < BN; j += st) { g_mem[j] = 0.f; g_wp[j] = 0.f; }
    for (int j = i; j < 2 * BN; j += st) g_outd[j] = 0.f;
    for (int j = i; j < 5 * BN; j += st) g_act[j] = 0.f;
    for (int j = i; j < BB * NOUTC; j += st) g_r[j] = 0.f;
}

// ---------------- W[d][e][o] = dmap * (sign[e] * |w[e][o]|) ---------------------
__global__ void k_prep(const float* __restrict__ w, const float* __restrict__ ws,
                       const float* __restrict__ dmap) {
    int i = blockIdx.x * 256 + threadIdx.x;
    int eo = i & (NN * NN - 1);
    g_W[i] = dmap[i] * (ws[eo >> 10] * fabsf(w[eo]));
}

// ------------- input projection: g_inp[t][b][n] = inputs[b][t][:] @ w_in --------
__global__ __launch_bounds__(256) void k_inp(const float* __restrict__ inputs,
                                             const float* __restrict__ w_in) {
    __shared__ float A_sm[64 * 33];
    __shared__ float W_sm[32 * 64];
    const int bx = blockIdx.x;
    const int mt = bx >> 4;
    const int nt = bx & 15;
    const int tid = threadIdx.x;
    const int mq = tid >> 4, nq = tid & 15;
    float acc[16];
#pragma unroll
    for (int i = 0; i < 16; i++) acc[i] = 0.f;

    for (int c0 = 0; c0 < NINC; c0 += 32) {
        int kk = tid & 31, rb = tid >> 5;
#pragma unroll
        for (int j = 0; j < 8; j++) {
            int row = rb + 8 * j;
            A_sm[row * 33 + kk] = inputs[row * (TT * NINC) + mt * NINC + c0 + kk];
        }
        int ol = tid & 63, kl = tid >> 6;
#pragma unroll
        for (int j = 0; j < 8; j++) {
            int k2 = kl + 4 * j;
            W_sm[k2 * 64 + ol] = w_in[(c0 + k2) * NN + nt * 64 + ol];
        }
        __syncthreads();
#pragma unroll
        for (int k2 = 0; k2 < 32; k2++) {
            float4 wv = *(const float4*)&W_sm[k2 * 64 + nq * 4];
            float a0 = A_sm[(mq * 4 + 0) * 33 + k2];
            float a1 = A_sm[(mq * 4 + 1) * 33 + k2];
            float a2 = A_sm[(mq * 4 + 2) * 33 + k2];
            float a3 = A_sm[(mq * 4 + 3) * 33 + k2];
            acc[0]  += a0 * wv.x; acc[1]  += a0 * wv.y; acc[2]  += a0 * wv.z; acc[3]  += a0 * wv.w;
            acc[4]  += a1 * wv.x; acc[5]  += a1 * wv.y; acc[6]  += a1 * wv.z; acc[7]  += a1 * wv.w;
            acc[8]  += a2 * wv.x; acc[9]  += a2 * wv.y; acc[10] += a2 * wv.z; acc[11] += a2 * wv.w;
            acc[12] += a3 * wv.x; acc[13] += a3 * wv.y; acc[14] += a3 * wv.z; acc[15] += a3 * wv.w;
        }
        __syncthreads();
    }
#pragma unroll
    for (int i = 0; i < 4; i++) {
        float4 v = make_float4(acc[i * 4], acc[i * 4 + 1], acc[i * 4 + 2], acc[i * 4 + 3]);
        *(float4*)&g_inp[mt * BN + (mq * 4 + i) * NN + nt * 64 + nq * 4] = v;
    }
}

// ---------------- cp.async helpers ----------------------------------------------
__device__ __forceinline__ void cpa16(void* s, const void* g) {
    unsigned a = (unsigned)__cvta_generic_to_shared(s);
    asm volatile("cp.async.cg.shared.global [%0], [%1], 16;" :: "r"(a), "l"(g));
}
#define CP_COMMIT() asm volatile("cp.async.commit_group;" ::: "memory")

// ---------------- recurrent GEMM: tile 64(b) x 256(o), split-K 32 ----------------
// k = kb*96 + c*16 + k2 over [0,3072); chunks never straddle delay boundaries.
__device__ __forceinline__ void load_chunk(int c, int st, int kb, int obase,
                                           int s1, int s2, int s4, int tid,
                                           float* Asm, float* Bsm) {
    int k0 = kb * 96 + c * 16;
    int d = k0 >> 10, e0 = k0 & (NN - 1);
    int sl = (d == 0) ? s1 : ((d == 1) ? s2 : s4);
    // A: 64 rows x 16 e, one float4 per thread
    int ab = tid >> 2, ae = (tid & 3) * 4;
    cpa16(&Asm[st * (64 * 20) + ab * 20 + ae],
          &g_act[sl * BN + ab * NN + e0 + ae]);
    // B: 16 rows x 256 o, four float4 per thread
    int br = tid >> 4, bc = (tid & 15) * 4;
    const float* Wg = &g_W[d * (NN * NN) + (e0 + br) * NN + obase + bc];
    float* Bs = &Bsm[st * (16 * 256) + br * 256 + bc];
#pragma unroll
    for (int j = 0; j < 4; j++) cpa16(Bs + j * 64, Wg + j * 64);
    CP_COMMIT();
}

__global__ __launch_bounds__(256) void k_step(int t) {
    __shared__ float A_sm[2 * 64 * 20];   // pitch 20 -> 16B-aligned rows
    __shared__ float B_sm[2 * 16 * 256];
    const int tid = threadIdx.x;
    const int ot = blockIdx.x >> 5;       // 4 col tiles of 256
    const int kb = blockIdx.x & 31;       // 32 K splits
    const int obase = ot * 256;
    const int tx = tid & 31, ty = tid >> 5;
    const int s1 = (t + 4) % 5, s2 = (t + 3) % 5, s4 = (t + 1) % 5;

    float acc[64];
#pragma unroll
    for (int i = 0; i < 64; i++) acc[i] = 0.f;

    load_chunk(0, 0, kb, obase, s1, s2, s4, tid, A_sm, B_sm);
    load_chunk(1, 1, kb, obase, s1, s2, s4, tid, A_sm, B_sm);

    for (int c = 0; c < NCHUNK; c++) {
        if (c < NCHUNK - 1) asm volatile("cp.async.wait_group 1;" ::: "memory");
        else                asm volatile("cp.async.wait_group 0;" ::: "memory");
        __syncthreads();
        const int st = c & 1;
        const float* As = &A_sm[st * (64 * 20) + ty * 8 * 20];
        const float* Bs = &B_sm[st * (16 * 256) + tx * 8];
#pragma unroll
        for (int k2 = 0; k2 < 16; k2++) {
            float4 b0 = *(const float4*)&Bs[k2 * 256];
            float4 b1 = *(const float4*)&Bs[k2 * 256 + 4];
#pragma unroll
            for (int i = 0; i < 8; i++) {
                float a = As[i * 20 + k2];          // warp-broadcast LDS.32
                acc[i * 8 + 0] += a * b0.x; acc[i * 8 + 1] += a * b0.y;
                acc[i * 8 + 2] += a * b0.z; acc[i * 8 + 3] += a * b0.w;
                acc[i * 8 + 4] += a * b1.x; acc[i * 8 + 5] += a * b1.y;
                acc[i * 8 + 6] += a * b1.z; acc[i * 8 + 7] += a * b1.w;
            }
        }
        __syncthreads();
        if (c + 2 < NCHUNK)
            load_chunk(c + 2, st, kb, obase, s1, s2, s4, tid, A_sm, B_sm);
    }

#pragma unroll
    for (int i = 0; i < 8; i++) {
        float* dst = &g_part[kb * BN + (ty * 8 + i) * NN + obase + tx * 8];
        *(float4*)dst       = make_float4(acc[i*8+0], acc[i*8+1], acc[i*8+2], acc[i*8+3]);
        *(float4*)(dst + 4) = make_float4(acc[i*8+4], acc[i*8+5], acc[i*8+6], acc[i*8+7]);
    }
}

// ---- update(t) [blocks 0..63] + readout of step t-1 [blocks 64..127] ------------
__global__ __launch_bounds__(256) void k_update(int t, const float* __restrict__ p,
                                                const float* __restrict__ w_out,
                                                float* __restrict__ out) {
    __shared__ float red[256];
    const int tid = threadIdx.x;

    if (blockIdx.x < 64) {
        if (t >= TT) return;
        int i4 = (blockIdx.x * 256 + tid) * 4;
        float4 mem  = *(float4*)&g_mem[i4];
        float4 wp   = *(float4*)&g_wp[i4];
        float4 pv   = *(const float4*)&p[i4 & (NN - 1)];
        float4 inpv = *(float4*)&g_inp[t * BN + i4];
        float4 syn  = make_float4(0.f, 0.f, 0.f, 0.f);
#pragma unroll
        for (int k = 0; k < SPLITK; k++) {          // deterministic fixed-order reduce
            float4 v = *(float4*)&g_part[k * BN + i4];
            syn.x += v.x; syn.y += v.y; syn.z += v.z; syn.w += v.w;
        }
        float o0 = mem.x > 1.f ? 1.f : 0.f;
        float o1 = mem.y > 1.f ? 1.f : 0.f;
        float o2 = mem.z > 1.f ? 1.f : 0.f;
        float o3 = mem.w > 1.f ? 1.f : 0.f;

        *(float4*)&g_act[(t % 5) * BN + i4] =
            make_float4(o0 * (1.f + wp.x), o1 * (1.f + wp.y),
                        o2 * (1.f + wp.z), o3 * (1.f + wp.w));
        *(float4*)&g_outd[(t & 1) * BN + i4] = make_float4(o0, o1, o2, o3);

        wp.x = 0.99f * wp.x + o0 * pv.x * (1.f + (pv.x < 0.f ? wp.x : 0.f));
        wp.y = 0.99f * wp.y + o1 * pv.y * (1.f + (pv.y < 0.f ? wp.y : 0.f));
        wp.z = 0.99f * wp.z + o2 * pv.z * (1.f + (pv.z < 0.f ? wp.z : 0.f));
        wp.w = 0.99f * wp.w + o3 * pv.w * (1.f + (pv.w < 0.f ? wp.w : 0.f));

        mem.x = 0.95f * mem.x + inpv.x + syn.x - o0;
        mem.y = 0.95f * mem.y + inpv.y + syn.y - o1;
        mem.z = 0.95f * mem.z + inpv.z + syn.z - o2;
        mem.w = 0.95f * mem.w + inpv.w + syn.w - o3;

        *(float4*)&g_wp[i4]  = wp;
        *(float4*)&g_mem[i4] = mem;
    } else {
        // readout of step t-1: r = 0.95 r + out(t-1) @ w_out
        if (t == 0) return;
        int b = blockIdx.x - 64;
        int o = tid & 31, ch = tid >> 5;
        const float* ob = &g_outd[((t - 1) & 1) * BN + b * NN];
        const float* wc = w_out + o;
        float s = 0.f;
        int e0 = ch * 128;
#pragma unroll 4
        for (int e = e0; e < e0 + 128; e++) s += ob[e] * wc[e * NOUTC];
        red[tid] = s;
        __syncthreads();
        if (tid < 32) {
            float h = 0.f;
#pragma unroll
            for (int c = 0; c < 8; c++) h += red[c * 32 + tid];
            float r = 0.95f * g_r[b * NOUTC + tid] + h;
            g_r[b * NOUTC + tid] = r;
            out[b * (TT * NOUTC) + (t - 1) * NOUTC + tid] = r;
        }
    }
}

extern "C" void kernel_launch(void* const* d_in, const int* in_sizes, int n_in,
                              void* d_out, int out_size) {
    (void)in_sizes; (void)n_in; (void)out_size;
    const float* inputs = (const float*)d_in[0];   // (B,T,NIN)
    const float* w      = (const float*)d_in[1];   // (N,N)
    const float* w_in   = (const float*)d_in[2];   // (NIN,N)
    const float* w_out  = (const float*)d_in[3];   // (N,NOUT)
    const float* ws     = (const float*)d_in[4];   // (N,)
    const float* dmap   = (const float*)d_in[5];   // (D,N,N)
    const float* p      = (const float*)d_in[6];   // (N,)
    // d_in[7] = delays [1,2,4] (fixed; baked into ring-slot math)
    float* out = (float*)d_out;                    // (B,T,NOUT) float32

    k_init<<<64, 256>>>();
    k_prep<<<(3 * NN * NN) / 256, 256>>>(w, ws, dmap);
    k_inp<<<TT * 16, 256>>>(inputs, w_in);

    for (int t = 0; t < TT; ++t) {
        k_step<<<128, 256>>>(t);                    // GEMM partials for step t
        k_update<<<128, 256>>>(t, p, w_out, out);   // update(t) + readout(t-1)
    }
    k_update<<<128, 256>>>(TT, p, w_out, out);      // final readout (t = TT-1)
}

// round 9
// speedup vs baseline: 1.3272x; 1.0740x over previous
#include <cuda_runtime.h>
#include <math.h>

#define BB    64
#define TT    400
#define NN    1024
#define NINC  128
#define NOUTC 32
#define BN    (BB * NN)
#define SPLITK 32
#define NCHUNK 6           // 96 K per GEMM CTA = 6 chunks of 16
#define NCTA  128          // persistent grid; < #SMs(148) so residency is guaranteed

// ---------------- device scratch (static: no runtime allocation) ----------------
__device__ __align__(128) float g_W[3 * NN * NN];     // 12 MB   dmap * sign * |w|
__device__ __align__(128) float g_inp[TT * BN];       // 105 MB  inputs @ w_in
__device__ __align__(128) float g_mem[BN];
__device__ __align__(128) float g_wp[BN];
__device__ __align__(128) float g_act[5 * BN];        // ring: out*(1+wp), slot t%5
__device__ __align__(128) float g_outd[2 * BN];       // spikes, double-buffer by t&1
__device__ __align__(128) float g_part[SPLITK * BN];  // split-K partials (8 MB)
__device__ __align__(128) float g_r[BB * NOUTC];      // readout leaky state
__device__ unsigned g_bar;                            // grid barrier counter

// ---------------- packed f32x2 helpers -------------------------------------------
#define FMA_X2(d, a, b, c) \
    asm("fma.rn.f32x2 %0, %1, %2, %3;" : "=l"(d) : "l"(a), "l"(b), "l"(c))
#define DUP_X2(d, s) \
    asm("mov.b64 %0, {%1, %1};" : "=l"(d) : "r"(__float_as_uint(s)))

// ---------------- zero state + barrier (runs at the start of every replay) -------
__global__ void k_init() {
    int i = blockIdx.x * 256 + threadIdx.x;
    const int st = 64 * 256;
    for (int j = i; j < BN; j += st) { g_mem[j] = 0.f; g_wp[j] = 0.f; }
    for (int j = i; j < 2 * BN; j += st) g_outd[j] = 0.f;
    for (int j = i; j < 5 * BN; j += st) g_act[j] = 0.f;
    for (int j = i; j < BB * NOUTC; j += st) g_r[j] = 0.f;
    if (i == 0) g_bar = 0u;
}

// ---------------- W[d][e][o] = dmap * (sign[e] * |w[e][o]|) ---------------------
__global__ void k_prep(const float* __restrict__ w, const float* __restrict__ ws,
                       const float* __restrict__ dmap) {
    int i = blockIdx.x * 256 + threadIdx.x;
    int eo = i & (NN * NN - 1);
    g_W[i] = dmap[i] * (ws[eo >> 10] * fabsf(w[eo]));
}

// ------------- input projection: g_inp[t][b][n] = inputs[b][t][:] @ w_in --------
__global__ __launch_bounds__(256) void k_inp(const float* __restrict__ inputs,
                                             const float* __restrict__ w_in) {
    __shared__ float A_sm[64 * 33];
    __shared__ float W_sm[32 * 64];
    const int mt = blockIdx.x >> 4;
    const int nt = blockIdx.x & 15;
    const int tid = threadIdx.x;
    const int mq = tid >> 4, nq = tid & 15;
    float acc[16];
#pragma unroll
    for (int i = 0; i < 16; i++) acc[i] = 0.f;

    for (int c0 = 0; c0 < NINC; c0 += 32) {
        int kk = tid & 31, rb = tid >> 5;
#pragma unroll
        for (int j = 0; j < 8; j++) {
            int row = rb + 8 * j;
            A_sm[row * 33 + kk] = inputs[row * (TT * NINC) + mt * NINC + c0 + kk];
        }
        int ol = tid & 63, kl = tid >> 6;
#pragma unroll
        for (int j = 0; j < 8; j++) {
            int k2 = kl + 4 * j;
            W_sm[k2 * 64 + ol] = w_in[(c0 + k2) * NN + nt * 64 + ol];
        }
        __syncthreads();
#pragma unroll
        for (int k2 = 0; k2 < 32; k2++) {
            float4 wv = *(const float4*)&W_sm[k2 * 64 + nq * 4];
            float a0 = A_sm[(mq * 4 + 0) * 33 + k2];
            float a1 = A_sm[(mq * 4 + 1) * 33 + k2];
            float a2 = A_sm[(mq * 4 + 2) * 33 + k2];
            float a3 = A_sm[(mq * 4 + 3) * 33 + k2];
            acc[0]  += a0 * wv.x; acc[1]  += a0 * wv.y; acc[2]  += a0 * wv.z; acc[3]  += a0 * wv.w;
            acc[4]  += a1 * wv.x; acc[5]  += a1 * wv.y; acc[6]  += a1 * wv.z; acc[7]  += a1 * wv.w;
            acc[8]  += a2 * wv.x; acc[9]  += a2 * wv.y; acc[10] += a2 * wv.z; acc[11] += a2 * wv.w;
            acc[12] += a3 * wv.x; acc[13] += a3 * wv.y; acc[14] += a3 * wv.z; acc[15] += a3 * wv.w;
        }
        __syncthreads();
    }
#pragma unroll
    for (int i = 0; i < 4; i++) {
        float4 v = make_float4(acc[i * 4], acc[i * 4 + 1], acc[i * 4 + 2], acc[i * 4 + 3]);
        *(float4*)&g_inp[mt * BN + (mq * 4 + i) * NN + nt * 64 + nq * 4] = v;
    }
}

// ---------------- cp.async helpers ----------------------------------------------
__device__ __forceinline__ void cpa16(void* s, const void* g) {
    unsigned a = (unsigned)__cvta_generic_to_shared(s);
    asm volatile("cp.async.cg.shared.global [%0], [%1], 16;" :: "r"(a), "l"(g));
}
#define CP_COMMIT() asm volatile("cp.async.commit_group;" ::: "memory")

__device__ __forceinline__ void load_chunk(int c, int st, int kb, int obase,
                                           int s1, int s2, int s4, int tid,
                                           float* Asm, float* Bsm) {
    int k0 = kb * 96 + c * 16;
    int d = k0 >> 10, e0 = k0 & (NN - 1);
    int sl = (d == 0) ? s1 : ((d == 1) ? s2 : s4);
    int ab = tid >> 2, ae = (tid & 3) * 4;                      // A: 64 x 16
    cpa16(&Asm[st * (64 * 20) + ab * 20 + ae],
          &g_act[sl * BN + ab * NN + e0 + ae]);
    int br = tid >> 4, bc = (tid & 15) * 4;                     // B: 16 x 256
    const float* Wg = &g_W[d * (NN * NN) + (e0 + br) * NN + obase + bc];
    float* Bs = &Bsm[st * (16 * 256) + br * 256 + bc];
#pragma unroll
    for (int j = 0; j < 4; j++) cpa16(Bs + j * 64, Wg + j * 64);
    CP_COMMIT();
}

// ---------------- grid barrier (monotone counter; NCTA resident CTAs) ------------
__device__ __forceinline__ void gbar(unsigned& target) {
    __syncthreads();
    if (threadIdx.x == 0) {
        __threadfence();
        atomicAdd(&g_bar, 1u);
        target += NCTA;
        unsigned v;
        asm volatile("ld.acquire.gpu.u32 %0, [%1];" : "=r"(v) : "l"(&g_bar) : "memory");
        while (v < target) {
            __nanosleep(32);
            asm volatile("ld.acquire.gpu.u32 %0, [%1];" : "=r"(v) : "l"(&g_bar) : "memory");
        }
    }
    __syncthreads();
}

// ---------------- persistent T-loop ----------------------------------------------
// phase A: all 128 CTAs run split-K GEMM for step t
// phase B: CTAs 0..63 state update(t);  CTAs 64..127 readout of step t-1
__global__ __launch_bounds__(256, 1) void k_loop(const float* __restrict__ p,
                                                 const float* __restrict__ w_out,
                                                 float* __restrict__ out) {
    __shared__ float A_sm[2 * 64 * 20];    // pitch 20 floats -> 16B-aligned rows
    __shared__ float B_sm[2 * 16 * 256];
    __shared__ float red[256];
    const int tid = threadIdx.x;
    const int bid = blockIdx.x;
    const int ot = bid >> 5, kb = bid & 31;
    const int obase = ot * 256;
    const int tx = tid & 31, ty = tid >> 5;
    unsigned target = 0;

    for (int t = 0; t <= TT; ++t) {
        // ================= phase A: GEMM(t) =================
        if (t < TT) {
            const int s1 = (t + 4) % 5, s2 = (t + 3) % 5, s4 = (t + 1) % 5;
            unsigned long long acc2[32];
#pragma unroll
            for (int i = 0; i < 32; i++) acc2[i] = 0ull;

            load_chunk(0, 0, kb, obase, s1, s2, s4, tid, A_sm, B_sm);
            load_chunk(1, 1, kb, obase, s1, s2, s4, tid, A_sm, B_sm);

            for (int c = 0; c < NCHUNK; c++) {
                if (c < NCHUNK - 1) asm volatile("cp.async.wait_group 1;" ::: "memory");
                else                asm volatile("cp.async.wait_group 0;" ::: "memory");
                __syncthreads();
                const int st = c & 1;
                const float* As = &A_sm[st * (64 * 20) + ty * 8 * 20];
                const float* Bs = &B_sm[st * (16 * 256) + tx * 8];
#pragma unroll
                for (int k2g = 0; k2g < 4; k2g++) {
                    float4 af[8];
#pragma unroll
                    for (int i = 0; i < 8; i++)               // LDS.128 broadcast
                        af[i] = *(const float4*)&As[i * 20 + k2g * 4];
#pragma unroll
                    for (int kk = 0; kk < 4; kk++) {
                        int k2 = k2g * 4 + kk;
                        ulonglong2 bl = *(const ulonglong2*)&Bs[k2 * 256];      // o pairs 0..3
                        ulonglong2 bh = *(const ulonglong2*)&Bs[k2 * 256 + 4];  // o pairs 4..7
#pragma unroll
                        for (int i = 0; i < 8; i++) {
                            float a = (kk == 0) ? af[i].x : (kk == 1) ? af[i].y
                                     : (kk == 2) ? af[i].z : af[i].w;
                            unsigned long long a2; DUP_X2(a2, a);
                            FMA_X2(acc2[i * 4 + 0], a2, bl.x, acc2[i * 4 + 0]);
                            FMA_X2(acc2[i * 4 + 1], a2, bl.y, acc2[i * 4 + 1]);
                            FMA_X2(acc2[i * 4 + 2], a2, bh.x, acc2[i * 4 + 2]);
                            FMA_X2(acc2[i * 4 + 3], a2, bh.y, acc2[i * 4 + 3]);
                        }
                    }
                }
                __syncthreads();
                if (c + 2 < NCHUNK)
                    load_chunk(c + 2, st, kb, obase, s1, s2, s4, tid, A_sm, B_sm);
            }
#pragma unroll
            for (int i = 0; i < 8; i++) {   // acc pairs are (o, o+1): contiguous floats
                float* dst = &g_part[kb * BN + (ty * 8 + i) * NN + obase + tx * 8];
                *(ulonglong2*)dst       = make_ulonglong2(acc2[i * 4 + 0], acc2[i * 4 + 1]);
                *(ulonglong2*)(dst + 4) = make_ulonglong2(acc2[i * 4 + 2], acc2[i * 4 + 3]);
            }
        }
        gbar(target);

        // ================= phase B: update(t) | readout(t-1) =================
        if (bid < 64) {
            if (t < TT) {
                int i4 = (bid * 256 + tid) * 4;
                float4 mem  = *(float4*)&g_mem[i4];
                float4 wp   = *(float4*)&g_wp[i4];
                float4 pv   = *(const float4*)&p[i4 & (NN - 1)];
                float4 inpv = *(float4*)&g_inp[t * BN + i4];
                float4 syn  = make_float4(0.f, 0.f, 0.f, 0.f);
#pragma unroll
                for (int k = 0; k < SPLITK; k++) {  // deterministic fixed-order reduce
                    float4 v = __ldcg((const float4*)&g_part[k * BN + i4]);
                    syn.x += v.x; syn.y += v.y; syn.z += v.z; syn.w += v.w;
                }
                float o0 = mem.x > 1.f ? 1.f : 0.f;
                float o1 = mem.y > 1.f ? 1.f : 0.f;
                float o2 = mem.z > 1.f ? 1.f : 0.f;
                float o3 = mem.w > 1.f ? 1.f : 0.f;

                *(float4*)&g_act[(t % 5) * BN + i4] =
                    make_float4(o0 * (1.f + wp.x), o1 * (1.f + wp.y),
                                o2 * (1.f + wp.z), o3 * (1.f + wp.w));
                *(float4*)&g_outd[(t & 1) * BN + i4] = make_float4(o0, o1, o2, o3);

                wp.x = 0.99f * wp.x + o0 * pv.x * (1.f + (pv.x < 0.f ? wp.x : 0.f));
                wp.y = 0.99f * wp.y + o1 * pv.y * (1.f + (pv.y < 0.f ? wp.y : 0.f));
                wp.z = 0.99f * wp.z + o2 * pv.z * (1.f + (pv.z < 0.f ? wp.z : 0.f));
                wp.w = 0.99f * wp.w + o3 * pv.w * (1.f + (pv.w < 0.f ? wp.w : 0.f));

                mem.x = 0.95f * mem.x + inpv.x + syn.x - o0;
                mem.y = 0.95f * mem.y + inpv.y + syn.y - o1;
                mem.z = 0.95f * mem.z + inpv.z + syn.z - o2;
                mem.w = 0.95f * mem.w + inpv.w + syn.w - o3;

                *(float4*)&g_wp[i4]  = wp;
                *(float4*)&g_mem[i4] = mem;
            }
        } else if (t > 0) {
            // readout(t-1): r = 0.95 r + out(t-1) @ w_out  (buffer (t-1)&1,
            // written in phase B of step t-1 — two barriers ago; no race with
            // this step's g_outd[t&1] writes)
            int b = bid - 64;
            int o = tid & 31, ch = tid >> 5;
            const float* ob = &g_outd[((t - 1) & 1) * BN + b * NN];
            float s = 0.f;
            int e0 = ch * 128;
#pragma unroll 4
            for (int e = e0; e < e0 + 128; e++)
                s += __ldcg(&ob[e]) * __ldg(&w_out[e * NOUTC + o]);
            red[tid] = s;
            __syncthreads();
            if (tid < 32) {
                float h = 0.f;
#pragma unroll
                for (int c = 0; c < 8; c++) h += red[c * 32 + tid];
                float r = 0.95f * g_r[b * NOUTC + tid] + h;
                g_r[b * NOUTC + tid] = r;
                out[b * (TT * NOUTC) + (t - 1) * NOUTC + tid] = r;
            }
            __syncthreads();
        }
        gbar(target);
    }
}

extern "C" void kernel_launch(void* const* d_in, const int* in_sizes, int n_in,
                              void* d_out, int out_size) {
    (void)in_sizes; (void)n_in; (void)out_size;
    const float* inputs = (const float*)d_in[0];   // (B,T,NIN)
    const float* w      = (const float*)d_in[1];   // (N,N)
    const float* w_in   = (const float*)d_in[2];   // (NIN,N)
    const float* w_out  = (const float*)d_in[3];   // (N,NOUT)
    const float* ws     = (const float*)d_in[4];   // (N,)
    const float* dmap   = (const float*)d_in[5];   // (D,N,N)
    const float* p      = (const float*)d_in[6];   // (N,)
    // d_in[7] = delays [1,2,4] (fixed; baked into ring-slot math)
    float* out = (float*)d_out;                    // (B,T,NOUT) float32

    k_init<<<64, 256>>>();
    k_prep<<<(3 * NN * NN) / 256, 256>>>(w, ws, dmap);
    k_inp<<<TT * 16, 256>>>(inputs, w_in);
    k_loop<<<NCTA, 256>>>(p, w_out, out);          // persistent: all 400 steps
}

// round 11
// speedup vs baseline: 1.3723x; 1.0339x over previous
#include <cuda_runtime.h>
#include <math.h>

#define BB    64
#define TT    400
#define NN    1024
#define NINC  128
#define NOUTC 32
#define BN    (BB * NN)
#define SPLITK 32
#define NCHUNK 6           // 96 K per GEMM CTA = 6 chunks of 16
#define NCTA  128          // persistent grid; < #SMs(148) so residency is guaranteed

// ---------------- device scratch (static: no runtime allocation) ----------------
__device__ __align__(128) float g_W[3 * NN * NN];     // 12 MB   dmap * sign * |w|
__device__ __align__(128) float g_inp[TT * BN];       // 105 MB  inputs @ w_in
__device__ __align__(128) float g_mem[BN];
__device__ __align__(128) float g_wp[BN];
__device__ __align__(128) float g_act[5 * BN];        // ring: out*(1+wp), slot t%5
__device__ __align__(128) float g_outd[2 * BN];       // spikes, double-buffer by t&1
__device__ __align__(128) float g_part[SPLITK * BN];  // split-K partials (8 MB)
__device__ __align__(128) float g_r[BB * NOUTC];      // readout leaky state
__device__ unsigned g_bar;                            // grid barrier counter

// ---------------- packed f32x2 helpers -------------------------------------------
#define FMA_X2(d, a, b, c) \
    asm("fma.rn.f32x2 %0, %1, %2, %3;" : "=l"(d) : "l"(a), "l"(b), "l"(c))
#define DUP_X2(d, s) \
    asm("mov.b64 %0, {%1, %1};" : "=l"(d) : "r"(__float_as_uint(s)))

// ---------------- zero state + barrier (runs at the start of every replay) -------
__global__ void k_init() {
    int i = blockIdx.x * 256 + threadIdx.x;
    const int st = 64 * 256;
    for (int j = i; j < BN; j += st) { g_mem[j] = 0.f; g_wp[j] = 0.f; }
    for (int j = i; j < 2 * BN; j += st) g_outd[j] = 0.f;
    for (int j = i; j < 5 * BN; j += st) g_act[j] = 0.f;
    for (int j = i; j < BB * NOUTC; j += st) g_r[j] = 0.f;
    if (i == 0) g_bar = 0u;
}

// ---------------- W[d][e][o] = dmap * (sign[e] * |w[e][o]|) ---------------------
__global__ void k_prep(const float* __restrict__ w, const float* __restrict__ ws,
                       const float* __restrict__ dmap) {
    int i = blockIdx.x * 256 + threadIdx.x;
    int eo = i & (NN * NN - 1);
    g_W[i] = dmap[i] * (ws[eo >> 10] * fabsf(w[eo]));
}

// ------------- input projection: g_inp[t][b][n] = inputs[b][t][:] @ w_in --------
__global__ __launch_bounds__(256) void k_inp(const float* __restrict__ inputs,
                                             const float* __restrict__ w_in) {
    __shared__ float A_sm[64 * 33];
    __shared__ float W_sm[32 * 64];
    const int mt = blockIdx.x >> 4;
    const int nt = blockIdx.x & 15;
    const int tid = threadIdx.x;
    const int mq = tid >> 4, nq = tid & 15;
    float acc[16];
#pragma unroll
    for (int i = 0; i < 16; i++) acc[i] = 0.f;

    for (int c0 = 0; c0 < NINC; c0 += 32) {
        int kk = tid & 31, rb = tid >> 5;
#pragma unroll
        for (int j = 0; j < 8; j++) {
            int row = rb + 8 * j;
            A_sm[row * 33 + kk] = inputs[row * (TT * NINC) + mt * NINC + c0 + kk];
        }
        int ol = tid & 63, kl = tid >> 6;
#pragma unroll
        for (int j = 0; j < 8; j++) {
            int k2 = kl + 4 * j;
            W_sm[k2 * 64 + ol] = w_in[(c0 + k2) * NN + nt * 64 + ol];
        }
        __syncthreads();
#pragma unroll
        for (int k2 = 0; k2 < 32; k2++) {
            float4 wv = *(const float4*)&W_sm[k2 * 64 + nq * 4];
            float a0 = A_sm[(mq * 4 + 0) * 33 + k2];
            float a1 = A_sm[(mq * 4 + 1) * 33 + k2];
            float a2 = A_sm[(mq * 4 + 2) * 33 + k2];
            float a3 = A_sm[(mq * 4 + 3) * 33 + k2];
            acc[0]  += a0 * wv.x; acc[1]  += a0 * wv.y; acc[2]  += a0 * wv.z; acc[3]  += a0 * wv.w;
            acc[4]  += a1 * wv.x; acc[5]  += a1 * wv.y; acc[6]  += a1 * wv.z; acc[7]  += a1 * wv.w;
            acc[8]  += a2 * wv.x; acc[9]  += a2 * wv.y; acc[10] += a2 * wv.z; acc[11] += a2 * wv.w;
            acc[12] += a3 * wv.x; acc[13] += a3 * wv.y; acc[14] += a3 * wv.z; acc[15] += a3 * wv.w;
        }
        __syncthreads();
    }
#pragma unroll
    for (int i = 0; i < 4; i++) {
        float4 v = make_float4(acc[i * 4], acc[i * 4 + 1], acc[i * 4 + 2], acc[i * 4 + 3]);
        *(float4*)&g_inp[mt * BN + (mq * 4 + i) * NN + nt * 64 + nq * 4] = v;
    }
}

// ---------------- cp.async helpers ----------------------------------------------
__device__ __forceinline__ void cpa16(void* s, const void* g) {
    unsigned a = (unsigned)__cvta_generic_to_shared(s);
    asm volatile("cp.async.cg.shared.global [%0], [%1], 16;" :: "r"(a), "l"(g));
}
#define CP_COMMIT() asm volatile("cp.async.commit_group;" ::: "memory")

__device__ __forceinline__ void load_chunk(int c, int st, int kb, int obase,
                                           int s1, int s2, int s4, int tid,
                                           float* Asm, float* Bsm) {
    int k0 = kb * 96 + c * 16;
    int d = k0 >> 10, e0 = k0 & (NN - 1);
    int sl = (d == 0) ? s1 : ((d == 1) ? s2 : s4);
    int ab = tid >> 2, ae = (tid & 3) * 4;                      // A: 64 x 16
    cpa16(&Asm[st * (64 * 20) + ab * 20 + ae],
          &g_act[sl * BN + ab * NN + e0 + ae]);
    int br = tid >> 4, bc = (tid & 15) * 4;                     // B: 16 x 256
    const float* Wg = &g_W[d * (NN * NN) + (e0 + br) * NN + obase + bc];
    float* Bs = &Bsm[st * (16 * 256) + br * 256 + bc];
#pragma unroll
    for (int j = 0; j < 4; j++) cpa16(Bs + j * 64, Wg + j * 64);
    CP_COMMIT();
}

// -------- grid barrier (R9-proven: monotone atomic counter, acquire poll) --------
__device__ __forceinline__ void gbar(unsigned& target) {
    __syncthreads();
    if (threadIdx.x == 0) {
        __threadfence();
        atomicAdd(&g_bar, 1u);
        target += NCTA;
        unsigned v;
        asm volatile("ld.acquire.gpu.u32 %0, [%1];" : "=r"(v) : "l"(&g_bar) : "memory");
        while (v < target) {
            __nanosleep(32);
            asm volatile("ld.acquire.gpu.u32 %0, [%1];" : "=r"(v) : "l"(&g_bar) : "memory");
        }
    }
    __syncthreads();
}

// ---------------- persistent T-loop ----------------------------------------------
// phase A: all 128 CTAs run split-K GEMM for step t
// phase B: CTAs 0..63 state update(t);  CTAs 64..127 readout of step t-1
__global__ __launch_bounds__(256, 1) void k_loop(const float* __restrict__ p,
                                                 const float* __restrict__ w_out,
                                                 float* __restrict__ out) {
    __shared__ float A_sm[2 * 64 * 20];    // pitch 20 floats -> 16B-aligned rows
    __shared__ float B_sm[2 * 16 * 256];
    __shared__ float red[256];
    const int tid = threadIdx.x;
    const int bid = blockIdx.x;
    const int ot = bid >> 5, kb = bid & 31;
    const int obase = ot * 256;
    const int tx = tid & 31, ty = tid >> 5;
    unsigned target = 0;

    for (int t = 0; t <= TT; ++t) {
        // ================= phase A: GEMM(t) =================
        if (t < TT) {
            const int s1 = (t + 4) % 5, s2 = (t + 3) % 5, s4 = (t + 1) % 5;
            unsigned long long acc2[32];
#pragma unroll
            for (int i = 0; i < 32; i++) acc2[i] = 0ull;

            load_chunk(0, 0, kb, obase, s1, s2, s4, tid, A_sm, B_sm);
            load_chunk(1, 1, kb, obase, s1, s2, s4, tid, A_sm, B_sm);

            for (int c = 0; c < NCHUNK; c++) {
                if (c < NCHUNK - 1) asm volatile("cp.async.wait_group 1;" ::: "memory");
                else                asm volatile("cp.async.wait_group 0;" ::: "memory");
                __syncthreads();
                const int st = c & 1;
                const float* As = &A_sm[st * (64 * 20) + ty * 8 * 20];
                // conflict-free B: each thread owns o = {tx*4..+3} and {128+tx*4..+3}
                const float* Bs = &B_sm[st * (16 * 256) + tx * 4];
#pragma unroll
                for (int k2g = 0; k2g < 4; k2g++) {
                    float4 af[8];
#pragma unroll
                    for (int i = 0; i < 8; i++)               // LDS.128 broadcast
                        af[i] = *(const float4*)&As[i * 20 + k2g * 4];
#pragma unroll
                    for (int kk = 0; kk < 4; kk++) {
                        int k2 = k2g * 4 + kk;
                        ulonglong2 bl = *(const ulonglong2*)&Bs[k2 * 256];        // 16B lane stride
                        ulonglong2 bh = *(const ulonglong2*)&Bs[k2 * 256 + 128];  // conflict-free
#pragma unroll
                        for (int i = 0; i < 8; i++) {
                            float a = (kk == 0) ? af[i].x : (kk == 1) ? af[i].y
                                     : (kk == 2) ? af[i].z : af[i].w;
                            unsigned long long a2; DUP_X2(a2, a);
                            FMA_X2(acc2[i * 4 + 0], a2, bl.x, acc2[i * 4 + 0]);
                            FMA_X2(acc2[i * 4 + 1], a2, bl.y, acc2[i * 4 + 1]);
                            FMA_X2(acc2[i * 4 + 2], a2, bh.x, acc2[i * 4 + 2]);
                            FMA_X2(acc2[i * 4 + 3], a2, bh.y, acc2[i * 4 + 3]);
                        }
                    }
                }
                __syncthreads();
                if (c + 2 < NCHUNK)
                    load_chunk(c + 2, st, kb, obase, s1, s2, s4, tid, A_sm, B_sm);
            }
#pragma unroll
            for (int i = 0; i < 8; i++) {   // acc pairs (o, o+1): contiguous floats
                float* dst = &g_part[kb * BN + (ty * 8 + i) * NN + obase + tx * 4];
                *(ulonglong2*)dst         = make_ulonglong2(acc2[i * 4 + 0], acc2[i * 4 + 1]);
                *(ulonglong2*)(dst + 128) = make_ulonglong2(acc2[i * 4 + 2], acc2[i * 4 + 3]);
            }
        }
        gbar(target);

        // ================= phase B: update(t) | readout(t-1) =================
        if (bid < 64) {
            if (t < TT) {
                int i4 = (bid * 256 + tid) * 4;
                float4 mem  = *(float4*)&g_mem[i4];
                float4 wp   = *(float4*)&g_wp[i4];
                float4 pv   = *(const float4*)&p[i4 & (NN - 1)];
                float4 inpv = *(float4*)&g_inp[t * BN + i4];
                float4 syn  = make_float4(0.f, 0.f, 0.f, 0.f);
#pragma unroll
                for (int k = 0; k < SPLITK; k++) {  // deterministic fixed-order reduce
                    float4 v = __ldcg((const float4*)&g_part[k * BN + i4]);
                    syn.x += v.x; syn.y += v.y; syn.z += v.z; syn.w += v.w;
                }
                float o0 = mem.x > 1.f ? 1.f : 0.f;
                float o1 = mem.y > 1.f ? 1.f : 0.f;
                float o2 = mem.z > 1.f ? 1.f : 0.f;
                float o3 = mem.w > 1.f ? 1.f : 0.f;

                *(float4*)&g_act[(t % 5) * BN + i4] =
                    make_float4(o0 * (1.f + wp.x), o1 * (1.f + wp.y),
                                o2 * (1.f + wp.z), o3 * (1.f + wp.w));
                *(float4*)&g_outd[(t & 1) * BN + i4] = make_float4(o0, o1, o2, o3);

                wp.x = 0.99f * wp.x + o0 * pv.x * (1.f + (pv.x < 0.f ? wp.x : 0.f));
                wp.y = 0.99f * wp.y + o1 * pv.y * (1.f + (pv.y < 0.f ? wp.y : 0.f));
                wp.z = 0.99f * wp.z + o2 * pv.z * (1.f + (pv.z < 0.f ? wp.z : 0.f));
                wp.w = 0.99f * wp.w + o3 * pv.w * (1.f + (pv.w < 0.f ? wp.w : 0.f));

                mem.x = 0.95f * mem.x + inpv.x + syn.x - o0;
                mem.y = 0.95f * mem.y + inpv.y + syn.y - o1;
                mem.z = 0.95f * mem.z + inpv.z + syn.z - o2;
                mem.w = 0.95f * mem.w + inpv.w + syn.w - o3;

                *(float4*)&g_wp[i4]  = wp;
                *(float4*)&g_mem[i4] = mem;
            }
        } else if (t > 0) {
            // readout(t-1): r = 0.95 r + out(t-1) @ w_out   (buffer (t-1)&1 was
            // written in phase B of step t-1 — one barrier ago; no race with
            // this step's g_outd[t&1] writes)
            int b = bid - 64;
            int o = tid & 31, ch = tid >> 5;
            const float* ob = &g_outd[((t - 1) & 1) * BN + b * NN];
            float s = 0.f;
            int e0 = ch * 128;
#pragma unroll 4
            for (int e = e0; e < e0 + 128; e++)
                s += __ldcg(&ob[e]) * __ldg(&w_out[e * NOUTC + o]);
            red[tid] = s;
            __syncthreads();
            if (tid < 32) {
                float h = 0.f;
#pragma unroll
                for (int c = 0; c < 8; c++) h += red[c * 32 + tid];
                float r = 0.95f * g_r[b * NOUTC + tid] + h;
                g_r[b * NOUTC + tid] = r;
                out[b * (TT * NOUTC) + (t - 1) * NOUTC + tid] = r;
            }
            __syncthreads();
        }
        gbar(target);
    }
}

extern "C" void kernel_launch(void* const* d_in, const int* in_sizes, int n_in,
                              void* d_out, int out_size) {
    (void)in_sizes; (void)n_in; (void)out_size;
    const float* inputs = (const float*)d_in[0];   // (B,T,NIN)
    const float* w      = (const float*)d_in[1];   // (N,N)
    const float* w_in   = (const float*)d_in[2];   // (NIN,N)
    const float* w_out  = (const float*)d_in[3];   // (N,NOUT)
    const float* ws     = (const float*)d_in[4];   // (N,)
    const float* dmap   = (const float*)d_in[5];   // (D,N,N)
    const float* p      = (const float*)d_in[6];   // (N,)
    // d_in[7] = delays [1,2,4] (fixed; baked into ring-slot math)
    float* out = (float*)d_out;                    // (B,T,NOUT) float32

    k_init<<<64, 256>>>();
    k_prep<<<(3 * NN * NN) / 256, 256>>>(w, ws, dmap);
    k_inp<<<TT * 16, 256>>>(inputs, w_in);
    k_loop<<<NCTA, 256>>>(p, w_out, out);          // persistent: all 400 steps
}

// round 12
// speedup vs baseline: 1.5457x; 1.1264x over previous
#include <cuda_runtime.h>
#include <math.h>

#define BB    64
#define TT    400
#define NN    1024
#define NINC  128
#define NOUTC 32
#define BN    (BB * NN)
#define SPLITK 32
#define NCHUNK 6           // 96 K per GEMM CTA = 6 chunks of 16
#define NCTA  128          // persistent grid; < #SMs(148) so residency is guaranteed
#define NTH   512          // 16 warps/CTA -> 4 warps per SMSP

// ---------------- device scratch (static: no runtime allocation) ----------------
__device__ __align__(128) float g_W[3 * NN * NN];     // 12 MB   dmap * sign * |w|
__device__ __align__(128) float g_inp[TT * BN];       // 105 MB  inputs @ w_in
__device__ __align__(128) float g_mem[BN];
__device__ __align__(128) float g_wp[BN];
__device__ __align__(128) float g_act[5 * BN];        // ring: out*(1+wp), slot t%5
__device__ __align__(128) float g_outd[2 * BN];       // spikes, double-buffer by t&1
__device__ __align__(128) float g_part[SPLITK * BN];  // split-K partials (8 MB)
__device__ __align__(128) float g_r[BB * NOUTC];      // readout leaky state
__device__ unsigned g_bar;                            // grid barrier counter

// ---------------- packed f32x2 helpers -------------------------------------------
#define FMA_X2(d, a, b, c) \
    asm("fma.rn.f32x2 %0, %1, %2, %3;" : "=l"(d) : "l"(a), "l"(b), "l"(c))
#define DUP_X2(d, s) \
    asm("mov.b64 %0, {%1, %1};" : "=l"(d) : "r"(__float_as_uint(s)))

// ---------------- zero state + barrier (runs at the start of every replay) -------
__global__ void k_init() {
    int i = blockIdx.x * 256 + threadIdx.x;
    const int st = 64 * 256;
    for (int j = i; j < BN; j += st) { g_mem[j] = 0.f; g_wp[j] = 0.f; }
    for (int j = i; j < 2 * BN; j += st) g_outd[j] = 0.f;
    for (int j = i; j < 5 * BN; j += st) g_act[j] = 0.f;
    for (int j = i; j < BB * NOUTC; j += st) g_r[j] = 0.f;
    if (i == 0) g_bar = 0u;
}

// ---------------- W[d][e][o] = dmap * (sign[e] * |w[e][o]|) ---------------------
__global__ void k_prep(const float* __restrict__ w, const float* __restrict__ ws,
                       const float* __restrict__ dmap) {
    int i = blockIdx.x * 256 + threadIdx.x;
    int eo = i & (NN * NN - 1);
    g_W[i] = dmap[i] * (ws[eo >> 10] * fabsf(w[eo]));
}

// ------------- input projection: g_inp[t][b][n] = inputs[b][t][:] @ w_in --------
__global__ __launch_bounds__(256) void k_inp(const float* __restrict__ inputs,
                                             const float* __restrict__ w_in) {
    __shared__ float A_sm[64 * 33];
    __shared__ float W_sm[32 * 64];
    const int mt = blockIdx.x >> 4;
    const int nt = blockIdx.x & 15;
    const int tid = threadIdx.x;
    const int mq = tid >> 4, nq = tid & 15;
    float acc[16];
#pragma unroll
    for (int i = 0; i < 16; i++) acc[i] = 0.f;

    for (int c0 = 0; c0 < NINC; c0 += 32) {
        int kk = tid & 31, rb = tid >> 5;
#pragma unroll
        for (int j = 0; j < 8; j++) {
            int row = rb + 8 * j;
            A_sm[row * 33 + kk] = inputs[row * (TT * NINC) + mt * NINC + c0 + kk];
        }
        int ol = tid & 63, kl = tid >> 6;
#pragma unroll
        for (int j = 0; j < 8; j++) {
            int k2 = kl + 4 * j;
            W_sm[k2 * 64 + ol] = w_in[(c0 + k2) * NN + nt * 64 + ol];
        }
        __syncthreads();
#pragma unroll
        for (int k2 = 0; k2 < 32; k2++) {
            float4 wv = *(const float4*)&W_sm[k2 * 64 + nq * 4];
            float a0 = A_sm[(mq * 4 + 0) * 33 + k2];
            float a1 = A_sm[(mq * 4 + 1) * 33 + k2];
            float a2 = A_sm[(mq * 4 + 2) * 33 + k2];
            float a3 = A_sm[(mq * 4 + 3) * 33 + k2];
            acc[0]  += a0 * wv.x; acc[1]  += a0 * wv.y; acc[2]  += a0 * wv.z; acc[3]  += a0 * wv.w;
            acc[4]  += a1 * wv.x; acc[5]  += a1 * wv.y; acc[6]  += a1 * wv.z; acc[7]  += a1 * wv.w;
            acc[8]  += a2 * wv.x; acc[9]  += a2 * wv.y; acc[10] += a2 * wv.z; acc[11] += a2 * wv.w;
            acc[12] += a3 * wv.x; acc[13] += a3 * wv.y; acc[14] += a3 * wv.z; acc[15] += a3 * wv.w;
        }
        __syncthreads();
    }
#pragma unroll
    for (int i = 0; i < 4; i++) {
        float4 v = make_float4(acc[i * 4], acc[i * 4 + 1], acc[i * 4 + 2], acc[i * 4 + 3]);
        *(float4*)&g_inp[mt * BN + (mq * 4 + i) * NN + nt * 64 + nq * 4] = v;
    }
}

// ---------------- cp.async helpers ----------------------------------------------
__device__ __forceinline__ void cpa16(void* s, const void* g) {
    unsigned a = (unsigned)__cvta_generic_to_shared(s);
    asm volatile("cp.async.cg.shared.global [%0], [%1], 16;" :: "r"(a), "l"(g));
}
#define CP_COMMIT() asm volatile("cp.async.commit_group;" ::: "memory")

// chunk = A 64x16 (256 float4, threads 0..255) + B 16x256 (1024 float4, 2/thread)
__device__ __forceinline__ void load_chunk(int c, int st, int kb, int obase,
                                           int s1, int s2, int s4, int tid,
                                           float* Asm, float* Bsm) {
    int k0 = kb * 96 + c * 16;
    int d = k0 >> 10, e0 = k0 & (NN - 1);
    int sl = (d == 0) ? s1 : ((d == 1) ? s2 : s4);
    if (tid < 256) {
        int ab = tid >> 2, ae = (tid & 3) * 4;                  // A: 64 x 16
        cpa16(&Asm[st * (64 * 20) + ab * 20 + ae],
              &g_act[sl * BN + ab * NN + e0 + ae]);
    }
    const float* Wg = &g_W[d * (NN * NN) + e0 * NN + obase];
    float* Bs = &Bsm[st * (16 * 256)];
#pragma unroll
    for (int j = 0; j < 2; j++) {                               // B: 16 x 256
        int idx = tid * 2 + j;
        int br = idx >> 6, bc = (idx & 63) * 4;
        cpa16(&Bs[br * 256 + bc], &Wg[br * NN + bc]);
    }
    CP_COMMIT();
}

// -------- grid barrier (R9/R11-proven: monotone atomic counter, acquire poll) ----
__device__ __forceinline__ void gbar(unsigned& target) {
    __syncthreads();
    if (threadIdx.x == 0) {
        __threadfence();
        atomicAdd(&g_bar, 1u);
        target += NCTA;
        unsigned v;
        asm volatile("ld.acquire.gpu.u32 %0, [%1];" : "=r"(v) : "l"(&g_bar) : "memory");
        while (v < target) {
            __nanosleep(32);
            asm volatile("ld.acquire.gpu.u32 %0, [%1];" : "=r"(v) : "l"(&g_bar) : "memory");
        }
    }
    __syncthreads();
}

// ---------------- persistent T-loop ----------------------------------------------
// phase A: all 128 CTAs run split-K GEMM for step t  (tile 64x256, 512 threads)
// phase B: CTAs 0..31 state update(t);  CTAs 32..95 readout of step t-1
__global__ __launch_bounds__(NTH, 1) void k_loop(const float* __restrict__ p,
                                                 const float* __restrict__ w_out,
                                                 float* __restrict__ out) {
    __shared__ float A_sm[2 * 64 * 20];    // pitch 20 floats -> 16B-aligned rows
    __shared__ float B_sm[2 * 16 * 256];
    __shared__ float red[NTH];
    const int tid = threadIdx.x;
    const int bid = blockIdx.x;
    const int ot = bid >> 5, kb = bid & 31;
    const int obase = ot * 256;
    const int tx = tid & 31, ty = tid >> 5;   // ty 0..15 -> 4 rows each
    unsigned target = 0;

    for (int t = 0; t <= TT; ++t) {
        // ================= phase A: GEMM(t) =================
        if (t < TT) {
            const int s1 = (t + 4) % 5, s2 = (t + 3) % 5, s4 = (t + 1) % 5;
            unsigned long long acc2[16];      // 4 rows x 8 cols (4 f32x2 pairs/row)
#pragma unroll
            for (int i = 0; i < 16; i++) acc2[i] = 0ull;

            load_chunk(0, 0, kb, obase, s1, s2, s4, tid, A_sm, B_sm);
            load_chunk(1, 1, kb, obase, s1, s2, s4, tid, A_sm, B_sm);

            for (int c = 0; c < NCHUNK; c++) {
                if (c < NCHUNK - 1) asm volatile("cp.async.wait_group 1;" ::: "memory");
                else                asm volatile("cp.async.wait_group 0;" ::: "memory");
                __syncthreads();
                const int st = c & 1;
                const float* As = &A_sm[st * (64 * 20) + ty * 4 * 20];
                // conflict-free B: thread owns o = {tx*4..+3} and {128+tx*4..+3}
                const float* Bs = &B_sm[st * (16 * 256) + tx * 4];
#pragma unroll
                for (int k2g = 0; k2g < 4; k2g++) {
                    float4 af[4];
#pragma unroll
                    for (int i = 0; i < 4; i++)               // LDS.128 broadcast
                        af[i] = *(const float4*)&As[i * 20 + k2g * 4];
#pragma unroll
                    for (int kk = 0; kk < 4; kk++) {
                        int k2 = k2g * 4 + kk;
                        ulonglong2 bl = *(const ulonglong2*)&Bs[k2 * 256];        // 16B stride
                        ulonglong2 bh = *(const ulonglong2*)&Bs[k2 * 256 + 128];  // conflict-free
#pragma unroll
                        for (int i = 0; i < 4; i++) {
                            float a = (kk == 0) ? af[i].x : (kk == 1) ? af[i].y
                                     : (kk == 2) ? af[i].z : af[i].w;
                            unsigned long long a2; DUP_X2(a2, a);
                            FMA_X2(acc2[i * 4 + 0], a2, bl.x, acc2[i * 4 + 0]);
                            FMA_X2(acc2[i * 4 + 1], a2, bl.y, acc2[i * 4 + 1]);
                            FMA_X2(acc2[i * 4 + 2], a2, bh.x, acc2[i * 4 + 2]);
                            FMA_X2(acc2[i * 4 + 3], a2, bh.y, acc2[i * 4 + 3]);
                        }
                    }
                }
                __syncthreads();
                if (c + 2 < NCHUNK)
                    load_chunk(c + 2, st, kb, obase, s1, s2, s4, tid, A_sm, B_sm);
            }
#pragma unroll
            for (int i = 0; i < 4; i++) {     // acc pairs (o, o+1): contiguous floats
                float* dst = &g_part[kb * BN + (ty * 4 + i) * NN + obase + tx * 4];
                *(ulonglong2*)dst         = make_ulonglong2(acc2[i * 4 + 0], acc2[i * 4 + 1]);
                *(ulonglong2*)(dst + 128) = make_ulonglong2(acc2[i * 4 + 2], acc2[i * 4 + 3]);
            }
        }
        gbar(target);

        // ================= phase B: update(t) | readout(t-1) =================
        if (bid < 32) {
            if (t < TT) {
                int i4 = (bid * NTH + tid) * 4;
                float4 mem  = *(float4*)&g_mem[i4];
                float4 wp   = *(float4*)&g_wp[i4];
                float4 pv   = *(const float4*)&p[i4 & (NN - 1)];
                float4 inpv = *(float4*)&g_inp[t * BN + i4];
                float4 syn  = make_float4(0.f, 0.f, 0.f, 0.f);
#pragma unroll
                for (int k = 0; k < SPLITK; k++) {  // deterministic fixed-order reduce
                    float4 v = __ldcg((const float4*)&g_part[k * BN + i4]);
                    syn.x += v.x; syn.y += v.y; syn.z += v.z; syn.w += v.w;
                }
                float o0 = mem.x > 1.f ? 1.f : 0.f;
                float o1 = mem.y > 1.f ? 1.f : 0.f;
                float o2 = mem.z > 1.f ? 1.f : 0.f;
                float o3 = mem.w > 1.f ? 1.f : 0.f;

                *(float4*)&g_act[(t % 5) * BN + i4] =
                    make_float4(o0 * (1.f + wp.x), o1 * (1.f + wp.y),
                                o2 * (1.f + wp.z), o3 * (1.f + wp.w));
                *(float4*)&g_outd[(t & 1) * BN + i4] = make_float4(o0, o1, o2, o3);

                wp.x = 0.99f * wp.x + o0 * pv.x * (1.f + (pv.x < 0.f ? wp.x : 0.f));
                wp.y = 0.99f * wp.y + o1 * pv.y * (1.f + (pv.y < 0.f ? wp.y : 0.f));
                wp.z = 0.99f * wp.z + o2 * pv.z * (1.f + (pv.z < 0.f ? wp.z : 0.f));
                wp.w = 0.99f * wp.w + o3 * pv.w * (1.f + (pv.w < 0.f ? wp.w : 0.f));

                mem.x = 0.95f * mem.x + inpv.x + syn.x - o0;
                mem.y = 0.95f * mem.y + inpv.y + syn.y - o1;
                mem.z = 0.95f * mem.z + inpv.z + syn.z - o2;
                mem.w = 0.95f * mem.w + inpv.w + syn.w - o3;

                *(float4*)&g_wp[i4]  = wp;
                *(float4*)&g_mem[i4] = mem;
            }
        } else if (bid < 96 && t > 0) {
            // readout(t-1): r = 0.95 r + out(t-1) @ w_out  (buffer (t-1)&1, written
            // in phase B of step t-1 — one barrier ago; no race with this step)
            int b = bid - 32;
            int o = tid & 31, ch = tid >> 5;          // ch 0..15, 64 elems each
            const float* ob = &g_outd[((t - 1) & 1) * BN + b * NN];
            float s = 0.f;
            int e0 = ch * 64;
#pragma unroll 4
            for (int e = e0; e < e0 + 64; e++)
                s += __ldcg(&ob[e]) * __ldg(&w_out[e * NOUTC + o]);
            red[tid] = s;
            __syncthreads();
            if (tid < 32) {
                float h = 0.f;
#pragma unroll
                for (int c = 0; c < 16; c++) h += red[c * 32 + tid];
                float r = 0.95f * g_r[b * NOUTC + tid] + h;
                g_r[b * NOUTC + tid] = r;
                out[b * (TT * NOUTC) + (t - 1) * NOUTC + tid] = r;
            }
            __syncthreads();
        }
        gbar(target);
    }
}

extern "C" void kernel_launch(void* const* d_in, const int* in_sizes, int n_in,
                              void* d_out, int out_size) {
    (void)in_sizes; (void)n_in; (void)out_size;
    const float* inputs = (const float*)d_in[0];   // (B,T,NIN)
    const float* w      = (const float*)d_in[1];   // (N,N)
    const float* w_in   = (const float*)d_in[2];   // (NIN,N)
    const float* w_out  = (const float*)d_in[3];   // (N,NOUT)
    const float* ws     = (const float*)d_in[4];   // (N,)
    const float* dmap   = (const float*)d_in[5];   // (D,N,N)
    const float* p      = (const float*)d_in[6];   // (N,)
    // d_in[7] = delays [1,2,4] (fixed; baked into ring-slot math)
    float* out = (float*)d_out;                    // (B,T,NOUT) float32

    k_init<<<64, 256>>>();
    k_prep<<<(3 * NN * NN) / 256, 256>>>(w, ws, dmap);
    k_inp<<<TT * 16, 256>>>(inputs, w_in);
    k_loop<<<NCTA, NTH>>>(p, w_out, out);          // persistent: all 400 steps
}

// round 13
// speedup vs baseline: 1.6599x; 1.0739x over previous
#include <cuda_runtime.h>
#include <math.h>

#define BB    64
#define TT    400
#define NN    1024
#define NINC  128
#define NOUTC 32
#define BN    (BB * NN)
#define SPLITK 32
#define NCHUNK 12          // 96 K per GEMM CTA = 12 chunks of 8
#define NCTA  128
#define NTH   512
#define BPITCH 520         // B smem row pitch (floats): hi at [0..255], lo at [260..515]
#define APITCH 12

// ---------------- device scratch -------------------------------------------------
__device__ __align__(128) float g_Wh[3 * NN * NN];    // tf32-hi of dmap*sign*|w|
__device__ __align__(128) float g_Wl[3 * NN * NN];    // tf32-lo residual
__device__ __align__(128) float g_inp[TT * BN];
__device__ __align__(128) float g_mem[BN];
__device__ __align__(128) float g_wp[BN];
__device__ __align__(128) float g_act[5 * BN];
__device__ __align__(128) float g_outd[2 * BN];
__device__ __align__(128) float g_part[SPLITK * BN];
__device__ __align__(128) float g_r[BB * NOUTC];
__device__ unsigned g_bar;

__device__ __forceinline__ unsigned tf32_hi(float x) {
    unsigned r; asm("cvt.rna.tf32.f32 %0, %1;" : "=r"(r) : "f"(x)); return r;
}
#define MMA_TF32(c, a0, a1, a2, a3, b0, b1) \
    asm("mma.sync.aligned.m16n8k8.row.col.f32.tf32.tf32.f32 " \
        "{%0,%1,%2,%3},{%4,%5,%6,%7},{%8,%9},{%0,%1,%2,%3};" \
        : "+f"((c)[0]), "+f"((c)[1]), "+f"((c)[2]), "+f"((c)[3]) \
        : "r"(a0), "r"(a1), "r"(a2), "r"(a3), "r"(b0), "r"(b1))

// ---------------- zero state + barrier -------------------------------------------
__global__ void k_init() {
    int i = blockIdx.x * 256 + threadIdx.x;
    const int st = 64 * 256;
    for (int j = i; j < BN; j += st) { g_mem[j] = 0.f; g_wp[j] = 0.f; }
    for (int j = i; j < 2 * BN; j += st) g_outd[j] = 0.f;
    for (int j = i; j < 5 * BN; j += st) g_act[j] = 0.f;
    for (int j = i; j < BB * NOUTC; j += st) g_r[j] = 0.f;
    if (i == 0) g_bar = 0u;
}

// ---------------- W prep: hi/lo tf32 split of dmap * sign * |w| ------------------
__global__ void k_prep(const float* __restrict__ w, const float* __restrict__ ws,
                       const float* __restrict__ dmap) {
    int i = blockIdx.x * 256 + threadIdx.x;
    int eo = i & (NN * NN - 1);
    float v = dmap[i] * (ws[eo >> 10] * fabsf(w[eo]));
    unsigned h = tf32_hi(v);
    float hf = __uint_as_float(h);
    g_Wh[i] = hf;
    g_Wl[i] = __uint_as_float(tf32_hi(v - hf));
}

// ------------- input projection (unchanged fp32) ---------------------------------
__global__ __launch_bounds__(256) void k_inp(const float* __restrict__ inputs,
                                             const float* __restrict__ w_in) {
    __shared__ float A_sm[64 * 33];
    __shared__ float W_sm[32 * 64];
    const int mt = blockIdx.x >> 4;
    const int nt = blockIdx.x & 15;
    const int tid = threadIdx.x;
    const int mq = tid >> 4, nq = tid & 15;
    float acc[16];
#pragma unroll
    for (int i = 0; i < 16; i++) acc[i] = 0.f;
    for (int c0 = 0; c0 < NINC; c0 += 32) {
        int kk = tid & 31, rb = tid >> 5;
#pragma unroll
        for (int j = 0; j < 8; j++) {
            int row = rb + 8 * j;
            A_sm[row * 33 + kk] = inputs[row * (TT * NINC) + mt * NINC + c0 + kk];
        }
        int ol = tid & 63, kl = tid >> 6;
#pragma unroll
        for (int j = 0; j < 8; j++) {
            int k2 = kl + 4 * j;
            W_sm[k2 * 64 + ol] = w_in[(c0 + k2) * NN + nt * 64 + ol];
        }
        __syncthreads();
#pragma unroll
        for (int k2 = 0; k2 < 32; k2++) {
            float4 wv = *(const float4*)&W_sm[k2 * 64 + nq * 4];
            float a0 = A_sm[(mq * 4 + 0) * 33 + k2];
            float a1 = A_sm[(mq * 4 + 1) * 33 + k2];
            float a2 = A_sm[(mq * 4 + 2) * 33 + k2];
            float a3 = A_sm[(mq * 4 + 3) * 33 + k2];
            acc[0]  += a0 * wv.x; acc[1]  += a0 * wv.y; acc[2]  += a0 * wv.z; acc[3]  += a0 * wv.w;
            acc[4]  += a1 * wv.x; acc[5]  += a1 * wv.y; acc[6]  += a1 * wv.z; acc[7]  += a1 * wv.w;
            acc[8]  += a2 * wv.x; acc[9]  += a2 * wv.y; acc[10] += a2 * wv.z; acc[11] += a2 * wv.w;
            acc[12] += a3 * wv.x; acc[13] += a3 * wv.y; acc[14] += a3 * wv.z; acc[15] += a3 * wv.w;
        }
        __syncthreads();
    }
#pragma unroll
    for (int i = 0; i < 4; i++) {
        float4 v = make_float4(acc[i * 4], acc[i * 4 + 1], acc[i * 4 + 2], acc[i * 4 + 3]);
        *(float4*)&g_inp[mt * BN + (mq * 4 + i) * NN + nt * 64 + nq * 4] = v;
    }
}

// ---------------- cp.async -------------------------------------------------------
__device__ __forceinline__ void cpa16(void* s, const void* g) {
    unsigned a = (unsigned)__cvta_generic_to_shared(s);
    asm volatile("cp.async.cg.shared.global [%0], [%1], 16;" :: "r"(a), "l"(g));
}
#define CP_COMMIT() asm volatile("cp.async.commit_group;" ::: "memory")

// chunk = 8 k-rows: A 64x8, B(hi+lo) 8x256
__device__ __forceinline__ void load_chunk(int c, int st, int kb, int obase,
                                           int s1, int s2, int s4, int tid,
                                           float* Asm, float* Bsm) {
    int k0 = kb * 96 + c * 8;
    int d = k0 >> 10, e0 = k0 & (NN - 1);
    int sl = (d == 0) ? s1 : ((d == 1) ? s2 : s4);
    if (tid < 128) {
        int ab = tid >> 1, ae = (tid & 1) * 4;
        cpa16(&Asm[st * (64 * APITCH) + ab * APITCH + ae],
              &g_act[sl * BN + ab * NN + e0 + ae]);
    }
    int br = tid >> 6, bc = (tid & 63) * 4;
    int goff = d * (NN * NN) + (e0 + br) * NN + obase + bc;
    float* Bs = &Bsm[st * (8 * BPITCH) + br * BPITCH + bc];
    cpa16(Bs, &g_Wh[goff]);
    cpa16(Bs + 260, &g_Wl[goff]);
    CP_COMMIT();
}

// -------- grid barrier (proven) --------------------------------------------------
__device__ __forceinline__ void gbar(unsigned& target) {
    __syncthreads();
    if (threadIdx.x == 0) {
        __threadfence();
        atomicAdd(&g_bar, 1u);
        target += NCTA;
        unsigned v;
        asm volatile("ld.acquire.gpu.u32 %0, [%1];" : "=r"(v) : "l"(&g_bar) : "memory");
        while (v < target) {
            __nanosleep(32);
            asm volatile("ld.acquire.gpu.u32 %0, [%1];" : "=r"(v) : "l"(&g_bar) : "memory");
        }
    }
    __syncthreads();
}

// ---------------- persistent T-loop ----------------------------------------------
__global__ __launch_bounds__(NTH, 1) void k_loop(const float* __restrict__ p,
                                                 const float* __restrict__ w_out,
                                                 float* __restrict__ out) {
    __shared__ float A_sm[2 * 64 * APITCH];
    __shared__ float B_sm[2 * 8 * BPITCH];
    __shared__ float red[NTH];
    const int tid = threadIdx.x;
    const int bid = blockIdx.x;
    const int ot = bid >> 5, kb = bid & 31;
    const int obase = ot * 256;
    const int lane = tid & 31, wid = tid >> 5;
    const int g = lane >> 2, ig = lane & 3;       // groupID / threadID_in_group
    const int mwarp = wid & 3, nwarp = wid >> 2;  // m-block 16, n-range 64
    unsigned target = 0;

    for (int t = 0; t <= TT; ++t) {
        // ================= phase A: GEMM(t) via 3xTF32 mma.sync =================
        if (t < TT) {
            const int s1 = (t + 4) % 5, s2 = (t + 3) % 5, s4 = (t + 1) % 5;
            float c[8][4];
#pragma unroll
            for (int nb = 0; nb < 8; nb++)
#pragma unroll
                for (int j = 0; j < 4; j++) c[nb][j] = 0.f;

            load_chunk(0, 0, kb, obase, s1, s2, s4, tid, A_sm, B_sm);
            load_chunk(1, 1, kb, obase, s1, s2, s4, tid, A_sm, B_sm);

            for (int cc = 0; cc < NCHUNK; cc++) {
                if (cc < NCHUNK - 1) asm volatile("cp.async.wait_group 1;" ::: "memory");
                else                 asm volatile("cp.async.wait_group 0;" ::: "memory");
                __syncthreads();
                const int st = cc & 1;
                const float* As = &A_sm[st * (64 * APITCH) + (mwarp * 16) * APITCH];
                const float* Bs = &B_sm[st * (8 * BPITCH)];
                // A fragment (rows g/g+8, k = ig/ig+4) + tf32 hi/lo split
                float a0f = As[(g) * APITCH + ig];
                float a1f = As[(g + 8) * APITCH + ig];
                float a2f = As[(g) * APITCH + ig + 4];
                float a3f = As[(g + 8) * APITCH + ig + 4];
                unsigned ah0 = tf32_hi(a0f), ah1 = tf32_hi(a1f);
                unsigned ah2 = tf32_hi(a2f), ah3 = tf32_hi(a3f);
                unsigned al0 = tf32_hi(a0f - __uint_as_float(ah0));
                unsigned al1 = tf32_hi(a1f - __uint_as_float(ah1));
                unsigned al2 = tf32_hi(a2f - __uint_as_float(ah2));
                unsigned al3 = tf32_hi(a3f - __uint_as_float(ah3));
#pragma unroll
                for (int nb = 0; nb < 8; nb++) {
                    int col = nwarp * 64 + nb * 8 + g;
                    unsigned bh0 = __float_as_uint(Bs[(ig) * BPITCH + col]);
                    unsigned bh1 = __float_as_uint(Bs[(ig + 4) * BPITCH + col]);
                    unsigned bl0 = __float_as_uint(Bs[(ig) * BPITCH + 260 + col]);
                    unsigned bl1 = __float_as_uint(Bs[(ig + 4) * BPITCH + 260 + col]);
                    MMA_TF32(c[nb], ah0, ah1, ah2, ah3, bh0, bh1);
                    MMA_TF32(c[nb], ah0, ah1, ah2, ah3, bl0, bl1);
                    MMA_TF32(c[nb], al0, al1, al2, al3, bh0, bh1);
                }
                __syncthreads();
                if (cc + 2 < NCHUNK)
                    load_chunk(cc + 2, st, kb, obase, s1, s2, s4, tid, A_sm, B_sm);
            }
            // epilogue: c[nb] -> partials (rows mwarp*16+g / +8, cols 2*ig,2*ig+1)
#pragma unroll
            for (int nb = 0; nb < 8; nb++) {
                int col = obase + nwarp * 64 + nb * 8 + 2 * ig;
                int r0 = mwarp * 16 + g;
                *(float2*)&g_part[kb * BN + r0 * NN + col]       = make_float2(c[nb][0], c[nb][1]);
                *(float2*)&g_part[kb * BN + (r0 + 8) * NN + col] = make_float2(c[nb][2], c[nb][3]);
            }
        }
        gbar(target);

        // ================= phase B: update(t) | readout(t-1) =================
        if (bid < 32) {
            if (t < TT) {
                int i4 = (bid * NTH + tid) * 4;
                float4 mem  = *(float4*)&g_mem[i4];
                float4 wp   = *(float4*)&g_wp[i4];
                float4 pv   = *(const float4*)&p[i4 & (NN - 1)];
                float4 inpv = *(float4*)&g_inp[t * BN + i4];
                float4 syn  = make_float4(0.f, 0.f, 0.f, 0.f);
#pragma unroll
                for (int k = 0; k < SPLITK; k++) {
                    float4 v = __ldcg((const float4*)&g_part[k * BN + i4]);
                    syn.x += v.x; syn.y += v.y; syn.z += v.z; syn.w += v.w;
                }
                float o0 = mem.x > 1.f ? 1.f : 0.f;
                float o1 = mem.y > 1.f ? 1.f : 0.f;
                float o2 = mem.z > 1.f ? 1.f : 0.f;
                float o3 = mem.w > 1.f ? 1.f : 0.f;

                *(float4*)&g_act[(t % 5) * BN + i4] =
                    make_float4(o0 * (1.f + wp.x), o1 * (1.f + wp.y),
                                o2 * (1.f + wp.z), o3 * (1.f + wp.w));
                *(float4*)&g_outd[(t & 1) * BN + i4] = make_float4(o0, o1, o2, o3);

                wp.x = 0.99f * wp.x + o0 * pv.x * (1.f + (pv.x < 0.f ? wp.x : 0.f));
                wp.y = 0.99f * wp.y + o1 * pv.y * (1.f + (pv.y < 0.f ? wp.y : 0.f));
                wp.z = 0.99f * wp.z + o2 * pv.z * (1.f + (pv.z < 0.f ? wp.z : 0.f));
                wp.w = 0.99f * wp.w + o3 * pv.w * (1.f + (pv.w < 0.f ? wp.w : 0.f));

                mem.x = 0.95f * mem.x + inpv.x + syn.x - o0;
                mem.y = 0.95f * mem.y + inpv.y + syn.y - o1;
                mem.z = 0.95f * mem.z + inpv.z + syn.z - o2;
                mem.w = 0.95f * mem.w + inpv.w + syn.w - o3;

                *(float4*)&g_wp[i4]  = wp;
                *(float4*)&g_mem[i4] = mem;
            }
        } else if (bid < 96 && t > 0) {
            int b = bid - 32;
            int o = tid & 31, ch = tid >> 5;
            const float* ob = &g_outd[((t - 1) & 1) * BN + b * NN];
            float s = 0.f;
            int e0 = ch * 64;
#pragma unroll 4
            for (int e = e0; e < e0 + 64; e++)
                s += __ldcg(&ob[e]) * __ldg(&w_out[e * NOUTC + o]);
            red[tid] = s;
            __syncthreads();
            if (tid < 32) {
                float h = 0.f;
#pragma unroll
                for (int cq = 0; cq < 16; cq++) h += red[cq * 32 + tid];
                float r = 0.95f * g_r[b * NOUTC + tid] + h;
                g_r[b * NOUTC + tid] = r;
                out[b * (TT * NOUTC) + (t - 1) * NOUTC + tid] = r;
            }
            __syncthreads();
        }
        gbar(target);
    }
}

extern "C" void kernel_launch(void* const* d_in, const int* in_sizes, int n_in,
                              void* d_out, int out_size) {
    (void)in_sizes; (void)n_in; (void)out_size;
    const float* inputs = (const float*)d_in[0];
    const float* w      = (const float*)d_in[1];
    const float* w_in   = (const float*)d_in[2];
    const float* w_out  = (const float*)d_in[3];
    const float* ws     = (const float*)d_in[4];
    const float* dmap   = (const float*)d_in[5];
    const float* p      = (const float*)d_in[6];
    float* out = (float*)d_out;

    k_init<<<64, 256>>>();
    k_prep<<<(3 * NN * NN) / 256, 256>>>(w, ws, dmap);
    k_inp<<<TT * 16, 256>>>(inputs, w_in);
    k_loop<<<NCTA, NTH>>>(p, w_out, out);
}